// round 15
// baseline (speedup 1.0000x reference)
#include <cuda_runtime.h>
#include <math.h>

#define T_   1024
#define B_   8
#define E_   1024
#define H_   16
#define HD   64
#define NB   4
#define DIN  256
#define TOPK 16
#define ROWS (T_*B_)          // 8192
#define BE   (B_*E_)          // 8192
#define SCALING 0.125f        // 64^-0.5

// ---------- scratch (device globals; no runtime allocation) ----------
__device__ float g_q[ROWS * E_];
__device__ float g_k[ROWS * E_];
__device__ float g_v[ROWS * E_];
__device__ float g_ctx[ROWS * E_];

// ---------- packed f32x2 helpers (exact lane-wise IEEE rn) ----------
__device__ __forceinline__ void dup2(unsigned long long& d, float f) {
    asm("mov.b64 %0, {%1, %1};" : "=l"(d) : "r"(__float_as_uint(f)));
}
__device__ __forceinline__ void fma2(unsigned long long& d,
                                     unsigned long long a,
                                     unsigned long long b,
                                     unsigned long long c) {
    asm("fma.rn.f32x2 %0, %1, %2, %3;" : "=l"(d) : "l"(a), "l"(b), "l"(c));
}
__device__ __forceinline__ void unpack2(float& lo, float& hi, unsigned long long p) {
    unsigned l, h;
    asm("mov.b64 {%0, %1}, %2;" : "=r"(l), "=r"(h) : "l"(p));
    lo = __uint_as_float(l); hi = __uint_as_float(h);
}

// =====================================================================
// Double-buffered block-diagonal GEMM core (BK=16, FFMA2, conflict-free
// B via paired LDS.64) — REVERTED to proven 245us config.
// =====================================================================
__device__ __forceinline__ void gemm_core(
    const float* __restrict__ X, const float* __restrict__ W,
    const float* __restrict__ bias, float* __restrict__ Y,
    float scale, int nb)
{
    const int m0 = blockIdx.x * 128;
    const int n0 = blockIdx.y * 128;
    const float* Wn = W + nb * DIN * DIN;

    __shared__ __align__(16) float As[2][16][128];
    __shared__ __align__(16) float Bs[2][16][128];

    const int tid = threadIdx.x;
    const int ty  = tid >> 4;
    const int tx2 = (tid & 15) * 2;
    const int arow = tid >> 1;
    const int akc  = (tid & 1) * 8;
    const int bkr  = tid >> 4;
    const int bcol = (tid & 15) * 8;

    const float* Xb = X + (long)m0 * E_ + nb * DIN;
    const float* Ap = Xb + (long)arow * E_;

    {
        float4 a0 = *(const float4*)(Ap + akc);
        float4 a1 = *(const float4*)(Ap + akc + 4);
        float4 b0 = *(const float4*)(Wn + bkr * DIN + n0 + bcol);
        float4 b1 = *(const float4*)(Wn + bkr * DIN + n0 + bcol + 4);
        As[0][akc+0][arow] = a0.x; As[0][akc+1][arow] = a0.y;
        As[0][akc+2][arow] = a0.z; As[0][akc+3][arow] = a0.w;
        As[0][akc+4][arow] = a1.x; As[0][akc+5][arow] = a1.y;
        As[0][akc+6][arow] = a1.z; As[0][akc+7][arow] = a1.w;
        *(float4*)&Bs[0][bkr][bcol]     = b0;
        *(float4*)&Bs[0][bkr][bcol + 4] = b1;
    }
    __syncthreads();

    unsigned long long accp[8][4];
#pragma unroll
    for (int i = 0; i < 8; i++)
#pragma unroll
        for (int j = 0; j < 4; j++) accp[i][j] = 0ull;

    for (int k0 = 0; k0 < 16; k0++) {
        const int cur = k0 & 1;
        float4 a0, a1, b0, b1;
        if (k0 < 15) {
            const int kn = (k0 + 1) * 16;
            a0 = *(const float4*)(Ap + kn + akc);
            a1 = *(const float4*)(Ap + kn + akc + 4);
            b0 = *(const float4*)(Wn + (kn + bkr) * DIN + n0 + bcol);
            b1 = *(const float4*)(Wn + (kn + bkr) * DIN + n0 + bcol + 4);
        }
#pragma unroll
        for (int kk = 0; kk < 16; kk++) {
            float af[8];
            *(float4*)(af)     = *(const float4*)&As[cur][kk][ty * 8];
            *(float4*)(af + 4) = *(const float4*)&As[cur][kk][ty * 8 + 4];
            unsigned long long bp[4];
#pragma unroll
            for (int j = 0; j < 4; j++)
                bp[j] = *(const unsigned long long*)&Bs[cur][kk][tx2 + 32 * j];
#pragma unroll
            for (int i = 0; i < 8; i++) {
                unsigned long long aa;
                dup2(aa, af[i]);
                fma2(accp[i][0], aa, bp[0], accp[i][0]);
                fma2(accp[i][1], aa, bp[1], accp[i][1]);
                fma2(accp[i][2], aa, bp[2], accp[i][2]);
                fma2(accp[i][3], aa, bp[3], accp[i][3]);
            }
        }
        if (k0 < 15) {
            const int nxt = cur ^ 1;
            As[nxt][akc+0][arow] = a0.x; As[nxt][akc+1][arow] = a0.y;
            As[nxt][akc+2][arow] = a0.z; As[nxt][akc+3][arow] = a0.w;
            As[nxt][akc+4][arow] = a1.x; As[nxt][akc+5][arow] = a1.y;
            As[nxt][akc+6][arow] = a1.z; As[nxt][akc+7][arow] = a1.w;
            *(float4*)&Bs[nxt][bkr][bcol]     = b0;
            *(float4*)&Bs[nxt][bkr][bcol + 4] = b1;
        }
        __syncthreads();
    }

    float2 bj[4];
#pragma unroll
    for (int j = 0; j < 4; j++) {
        bj[j].x = bias[nb * DIN + n0 + tx2 + 32 * j];
        bj[j].y = bias[nb * DIN + n0 + tx2 + 32 * j + 1];
    }

#pragma unroll
    for (int i = 0; i < 8; i++) {
        const long row = m0 + ty * 8 + i;
        float* yp = Y + row * E_ + nb * DIN + n0;
#pragma unroll
        for (int j = 0; j < 4; j++) {
            float lo, hi;
            unpack2(lo, hi, accp[i][j]);
            *(float2*)(yp + tx2 + 32 * j) =
                make_float2((lo + bj[j].x) * scale, (hi + bj[j].y) * scale);
        }
    }
}

__global__ void __launch_bounds__(256) qkv_gemm(
    const float* __restrict__ Q, const float* __restrict__ Kin,
    const float* __restrict__ V,
    const float* __restrict__ Wq, const float* __restrict__ bq,
    const float* __restrict__ Wk, const float* __restrict__ bk,
    const float* __restrict__ Wv, const float* __restrict__ bv,
    float* __restrict__ Yq, float* __restrict__ Yk, float* __restrict__ Yv)
{
    const int op = blockIdx.z >> 2;
    const int nb = blockIdx.z & 3;
    if (op == 0)      gemm_core(Q,   Wq, bq, Yq, SCALING, nb);
    else if (op == 1) gemm_core(Kin, Wk, bk, Yk, 1.0f,    nb);
    else              gemm_core(V,   Wv, bv, Yv, 1.0f,    nb);
}

__global__ void __launch_bounds__(256) o_gemm(
    const float* __restrict__ X, const float* __restrict__ W,
    const float* __restrict__ bias, float* __restrict__ Y)
{
    gemm_core(X, W, bias, Y, 1.0f, blockIdx.z);
}

// =====================================================================
// Fused attention — R12 score/topk/ctx EXACT; loader split: warps 0-3
// score only (no load work), warps 4-7 prefetch next tile into regs
// during scoring, STS after barrier. Barrier count unchanged.
// =====================================================================
#define QT  16
#define KT  128
#define SP  1032
#define NTH 256

__device__ __forceinline__ unsigned fmono(float f) {
    unsigned b = __float_as_uint(f);
    return (b & 0x80000000u) ? ~b : (b | 0x80000000u);
}
__device__ __forceinline__ float fdemono(unsigned m) {
    unsigned b = (m & 0x80000000u) ? (m & 0x7fffffffu) : ~m;
    return __uint_as_float(b);
}

// branchless sorted-top4 insertion; strict > keeps earliest pos on ties
#define INS4(nv, np)                                                   \
    do {                                                               \
        bool c0 = (nv) > v0, c1 = (nv) > v1,                           \
             c2 = (nv) > v2, c3 = (nv) > v3;                           \
        v3 = c3 ? (c2 ? v2 : (nv)) : v3;                               \
        p3 = c3 ? (c2 ? p2 : (np)) : p3;                               \
        v2 = c2 ? (c1 ? v1 : (nv)) : v2;                               \
        p2 = c2 ? (c1 ? p1 : (np)) : p2;                               \
        v1 = c1 ? (c0 ? v0 : (nv)) : v1;                               \
        p1 = c1 ? (c0 ? p0 : (np)) : p1;                               \
        v0 = c0 ? (nv) : v0;                                           \
        p0 = c0 ? (np) : p0;                                           \
    } while (0)

// strided conflict-free scan (positions ascend per lane -> min-pos ties)
#define SCAN_TOP4(Sr)                                                  \
    do {                                                               \
        v0 = v1 = v2 = v3 = -INFINITY;                                 \
        p0 = p1 = p2 = p3 = 0;                                         \
        _Pragma("unroll")                                              \
        for (int t = 0; t < 32; t++) {                                 \
            float nv = (Sr)[lane + 32 * t];                            \
            int   np = lane + 32 * t;                                  \
            INS4(nv, np);                                              \
        }                                                              \
    } while (0)

__global__ void __launch_bounds__(NTH, 2) attn_kernel(
    const float* __restrict__ qg, const float* __restrict__ kg,
    const float* __restrict__ vg, float* __restrict__ ctxg)
{
    extern __shared__ float sm[];
    float* S    = sm;                      // QT*SP              (66048 B)
    float* ks   = S + QT * SP;             // 128 x 64 swizzled  (32768 B)
    float* qp   = ks + KT * 64;            // [d][pair] 64 x 8 x float2 (4096 B)
    float* tpp  = qp + 64 * 8 * 2;         // QT*16
    int*   tpi  = (int*)(tpp + QT * TOPK); // QT*16

    const int tid = threadIdx.x;
    const int qt  = blockIdx.x;            // 0..63
    const int bh  = blockIdx.y;            // 0..127
    const int bb  = bh >> 4;
    const int hh  = bh & 15;
    const long base = (long)bb * E_ + hh * HD;

    const int lane = tid & 31;
    const int w    = tid >> 5;             // warp 0..7

    // ---- build q pairs: qp[(d*8+p)*2] = {q[2p][d], q[2p+1][d]} ----
#pragma unroll
    for (int e = tid; e < 512; e += NTH) {
        const int p = e >> 6;              // 0..7
        const int d = e & 63;
        const float* q0 = qg + (long)(qt * QT + 2 * p) * BE + base + d;
        *(float2*)&qp[(d * 8 + p) * 2] = make_float2(q0[0], q0[BE]);
    }

    // ---- prologue: ALL threads load tile 0 (8 float4 each) ----
#pragma unroll
    for (int f = tid; f < KT * 16; f += NTH) {
        int key = f >> 4, d4x = f & 15;
        float4 v4 = *(const float4*)(kg + (long)key * BE + base + d4x * 4);
        *(float4*)&ks[key * 64 + ((d4x ^ (key & 7)) << 2)] = v4;
    }
    __syncthreads();

    // score warp roles (w<4): g = pair group (pairs g*4..g*4+3), s = key half
    const int g = (w >> 1) & 1;
    const int s = w & 1;
    const int lane7 = lane & 7;
    const float* ka_ptr = ks + (s * 64 + lane) * 64;
    const float* kb_ptr = ka_ptr + 32 * 64;

    // loader thread indices (warps 4-7: lt = 0..127, 16 float4 each)
    const int lt = tid - 128;

    for (int kt = 0; kt < T_ / KT; kt++) {
        float4 st[16];
        if (w < 4) {
            unsigned long long acc[4][2];
#pragma unroll
            for (int p = 0; p < 4; p++) { acc[p][0] = 0ull; acc[p][1] = 0ull; }

#pragma unroll
            for (int d4 = 0; d4 < 16; d4++) {
                const int c = (d4 ^ lane7) << 2;
                float4 Ka = *(const float4*)(ka_ptr + c);
                float4 Kb = *(const float4*)(kb_ptr + c);
#pragma unroll
                for (int dd = 0; dd < 4; dd++) {
                    unsigned long long kda, kdb;
                    dup2(kda, (&Ka.x)[dd]);
                    dup2(kdb, (&Kb.x)[dd]);
                    const float* qpd = qp + (((d4 * 4 + dd) * 8) + g * 4) * 2;
                    ulonglong2 q01 = *(const ulonglong2*)(qpd);
                    ulonglong2 q23 = *(const ulonglong2*)(qpd + 4);
                    fma2(acc[0][0], q01.x, kda, acc[0][0]);
                    fma2(acc[0][1], q01.x, kdb, acc[0][1]);
                    fma2(acc[1][0], q01.y, kda, acc[1][0]);
                    fma2(acc[1][1], q01.y, kdb, acc[1][1]);
                    fma2(acc[2][0], q23.x, kda, acc[2][0]);
                    fma2(acc[2][1], q23.x, kdb, acc[2][1]);
                    fma2(acc[3][0], q23.y, kda, acc[3][0]);
                    fma2(acc[3][1], q23.y, kdb, acc[3][1]);
                }
            }

            const int col = kt * KT + s * 64 + lane;
#pragma unroll
            for (int p = 0; p < 4; p++) {
                float lo, hi;
                unpack2(lo, hi, acc[p][0]);
                S[(g * 8 + 2 * p    ) * SP + col] = lo;
                S[(g * 8 + 2 * p + 1) * SP + col] = hi;
                unpack2(lo, hi, acc[p][1]);
                S[(g * 8 + 2 * p    ) * SP + col + 32] = lo;
                S[(g * 8 + 2 * p + 1) * SP + col + 32] = hi;
            }
        } else if (kt < T_ / KT - 1) {
            // loader warps: prefetch next tile into registers (MLP=16)
            const float* kgn = kg + (long)(kt + 1) * KT * BE + base;
#pragma unroll
            for (int u = 0; u < 16; u++) {
                int f = lt + 128 * u;
                int key = f >> 4, d4x = f & 15;
                st[u] = *(const float4*)(kgn + (long)key * BE + d4x * 4);
            }
        }
        __syncthreads();                    // scores done reading ks

        if (w >= 4 && kt < T_ / KT - 1) {
#pragma unroll
            for (int u = 0; u < 16; u++) {
                int f = lt + 128 * u;
                int key = f >> 4, d4x = f & 15;
                *(float4*)&ks[key * 64 + ((d4x ^ (key & 7)) << 2)] = st[u];
            }
        }
        __syncthreads();                    // new tile visible
    }

    // ---- per-row top-16 + softmax: warp w owns rows 2w, 2w+1 ----
    for (int r = w * 2; r < w * 2 + 2; r++) {
        float* Sr = S + r * SP;

        float v0, v1, v2, v3;
        int   p0, p1, p2, p3;
        SCAN_TOP4(Sr);
        int cnt = 4;

        unsigned kb = fmono(v0);
        unsigned mk = __reduce_max_sync(0xffffffffu, kb);
        unsigned cp = (kb == mk) ? (unsigned)p0 : 0xffffffffu;
        unsigned bp = __reduce_min_sync(0xffffffffu, cp);
        const float m = fdemono(mk);

        // softmax denominator — EXACT established pattern (bitwise identical)
        float s0 = 0.f, s1 = 0.f, s2 = 0.f, s3 = 0.f;
#pragma unroll
        for (int t = 0; t < 32; t += 4) {
            s0 += __expf(Sr[lane + 32 * (t + 0)] - m);
            s1 += __expf(Sr[lane + 32 * (t + 1)] - m);
            s2 += __expf(Sr[lane + 32 * (t + 2)] - m);
            s3 += __expf(Sr[lane + 32 * (t + 3)] - m);
        }
        float sum = (s0 + s1) + (s2 + s3);
#pragma unroll
        for (int o = 16; o; o >>= 1) sum += __shfl_xor_sync(~0u, sum, o);
        const float inv = 1.0f / sum;

        if (lane == 0) { tpi[r * TOPK] = (int)bp; tpp[r * TOPK] = inv; }
        if ((int)(bp & 31) == lane) {
            Sr[bp] = -INFINITY;
            v0=v1;p0=p1; v1=v2;p1=p2; v2=v3;p2=p3; v3=-INFINITY;
            if (--cnt == 0) { SCAN_TOP4(Sr); cnt = 4; }
        }

        for (int it = 1; it < TOPK; it++) {
            kb = fmono(v0);
            mk = __reduce_max_sync(0xffffffffu, kb);
            cp = (kb == mk) ? (unsigned)p0 : 0xffffffffu;
            bp = __reduce_min_sync(0xffffffffu, cp);
            if (lane == 0) {
                tpi[r * TOPK + it] = (int)bp;
                tpp[r * TOPK + it] = __expf(fdemono(mk) - m) * inv;
            }
            if ((int)(bp & 31) == lane) {
                Sr[bp] = -INFINITY;
                v0=v1;p0=p1; v1=v2;p1=p2; v2=v3;p2=p3; v3=-INFINITY;
                if (--cnt == 0) { SCAN_TOP4(Sr); cnt = 4; }
            }
        }
    }
    __syncthreads();

    // ---- sparse ctx: 16-key gather; 16 threads x float4 per row ----
    const int cr = tid >> 4;               // 0..15 query row
    const int d0 = (tid & 15) * 4;         // 0..60
    float c0 = 0.f, c1 = 0.f, c2 = 0.f, c3 = 0.f;
#pragma unroll
    for (int i = 0; i < TOPK; i++) {
        const int   idx = tpi[cr * TOPK + i];
        const float p   = tpp[cr * TOPK + i];
        float4 a = *(const float4*)(vg + (long)idx * BE + base + d0);
        c0 = fmaf(p, a.x, c0); c1 = fmaf(p, a.y, c1);
        c2 = fmaf(p, a.z, c2); c3 = fmaf(p, a.w, c3);
    }
    *(float4*)(ctxg + (long)(qt * QT + cr) * BE + base + d0) =
        make_float4(c0, c1, c2, c3);
}

// =====================================================================
// launch
// =====================================================================
static const size_t ATTN_SMEM =
    (size_t)(QT * SP + KT * 64 + 64 * 8 * 2 + QT * TOPK + QT * TOPK) * 4;

extern "C" void kernel_launch(void* const* d_in, const int* in_sizes, int n_in,
                              void* d_out, int out_size)
{
    const float* query  = (const float*)d_in[0];
    const float* key_in = (const float*)d_in[1];
    const float* value  = (const float*)d_in[2];
    const float* Wq = (const float*)d_in[3];
    const float* bq = (const float*)d_in[4];
    const float* Wk = (const float*)d_in[5];
    const float* bk = (const float*)d_in[6];
    const float* Wv = (const float*)d_in[7];
    const float* bv = (const float*)d_in[8];
    const float* Wo = (const float*)d_in[9];
    const float* bo = (const float*)d_in[10];
    float* out = (float*)d_out;

    float *pq, *pk, *pv, *pctx;
    cudaGetSymbolAddress((void**)&pq,   g_q);
    cudaGetSymbolAddress((void**)&pk,   g_k);
    cudaGetSymbolAddress((void**)&pv,   g_v);
    cudaGetSymbolAddress((void**)&pctx, g_ctx);

    cudaFuncSetAttribute(attn_kernel,
                         cudaFuncAttributeMaxDynamicSharedMemorySize,
                         (int)ATTN_SMEM);

    dim3 gq(ROWS / 128, DIN / 128, 12);
    qkv_gemm<<<gq, 256>>>(query, key_in, value,
                          Wq, bq, Wk, bk, Wv, bv, pq, pk, pv);

    dim3 ag(T_ / QT, B_ * H_);
    attn_kernel<<<ag, NTH, ATTN_SMEM>>>(pq, pk, pv, pctx);

    dim3 go(ROWS / 128, DIN / 128, NB);
    o_gemm<<<go, 256>>>(pctx, Wo, bo, out);
}

// round 16
// speedup vs baseline: 1.0854x; 1.0854x over previous
#include <cuda_runtime.h>
#include <math.h>

#define T_   1024
#define B_   8
#define E_   1024
#define H_   16
#define HD   64
#define NB   4
#define DIN  256
#define TOPK 16
#define ROWS (T_*B_)          // 8192
#define BE   (B_*E_)          // 8192
#define SCALING 0.125f        // 64^-0.5

// ---------- scratch (device globals; no runtime allocation) ----------
__device__ float g_q[ROWS * E_];
__device__ float g_k[ROWS * E_];
__device__ float g_v[ROWS * E_];
__device__ float g_ctx[ROWS * E_];

// ---------- packed f32x2 helpers (exact lane-wise IEEE rn) ----------
__device__ __forceinline__ void dup2(unsigned long long& d, float f) {
    asm("mov.b64 %0, {%1, %1};" : "=l"(d) : "r"(__float_as_uint(f)));
}
__device__ __forceinline__ void fma2(unsigned long long& d,
                                     unsigned long long a,
                                     unsigned long long b,
                                     unsigned long long c) {
    asm("fma.rn.f32x2 %0, %1, %2, %3;" : "=l"(d) : "l"(a), "l"(b), "l"(c));
}
__device__ __forceinline__ void unpack2(float& lo, float& hi, unsigned long long p) {
    unsigned l, h;
    asm("mov.b64 {%0, %1}, %2;" : "=r"(l), "=r"(h) : "l"(p));
    lo = __uint_as_float(l); hi = __uint_as_float(h);
}

// =====================================================================
// Double-buffered block-diagonal GEMM core (BK=16, FFMA2, conflict-free
// B via paired LDS.64) — proven 245us qkv config.
// =====================================================================
__device__ __forceinline__ void gemm_core(
    const float* __restrict__ X, const float* __restrict__ W,
    const float* __restrict__ bias, float* __restrict__ Y,
    float scale, int nb)
{
    const int m0 = blockIdx.x * 128;
    const int n0 = blockIdx.y * 128;
    const float* Wn = W + nb * DIN * DIN;

    __shared__ __align__(16) float As[2][16][128];
    __shared__ __align__(16) float Bs[2][16][128];

    const int tid = threadIdx.x;
    const int ty  = tid >> 4;
    const int tx2 = (tid & 15) * 2;
    const int arow = tid >> 1;
    const int akc  = (tid & 1) * 8;
    const int bkr  = tid >> 4;
    const int bcol = (tid & 15) * 8;

    const float* Xb = X + (long)m0 * E_ + nb * DIN;
    const float* Ap = Xb + (long)arow * E_;

    {
        float4 a0 = *(const float4*)(Ap + akc);
        float4 a1 = *(const float4*)(Ap + akc + 4);
        float4 b0 = *(const float4*)(Wn + bkr * DIN + n0 + bcol);
        float4 b1 = *(const float4*)(Wn + bkr * DIN + n0 + bcol + 4);
        As[0][akc+0][arow] = a0.x; As[0][akc+1][arow] = a0.y;
        As[0][akc+2][arow] = a0.z; As[0][akc+3][arow] = a0.w;
        As[0][akc+4][arow] = a1.x; As[0][akc+5][arow] = a1.y;
        As[0][akc+6][arow] = a1.z; As[0][akc+7][arow] = a1.w;
        *(float4*)&Bs[0][bkr][bcol]     = b0;
        *(float4*)&Bs[0][bkr][bcol + 4] = b1;
    }
    __syncthreads();

    unsigned long long accp[8][4];
#pragma unroll
    for (int i = 0; i < 8; i++)
#pragma unroll
        for (int j = 0; j < 4; j++) accp[i][j] = 0ull;

    for (int k0 = 0; k0 < 16; k0++) {
        const int cur = k0 & 1;
        float4 a0, a1, b0, b1;
        if (k0 < 15) {
            const int kn = (k0 + 1) * 16;
            a0 = *(const float4*)(Ap + kn + akc);
            a1 = *(const float4*)(Ap + kn + akc + 4);
            b0 = *(const float4*)(Wn + (kn + bkr) * DIN + n0 + bcol);
            b1 = *(const float4*)(Wn + (kn + bkr) * DIN + n0 + bcol + 4);
        }
#pragma unroll
        for (int kk = 0; kk < 16; kk++) {
            float af[8];
            *(float4*)(af)     = *(const float4*)&As[cur][kk][ty * 8];
            *(float4*)(af + 4) = *(const float4*)&As[cur][kk][ty * 8 + 4];
            unsigned long long bp[4];
#pragma unroll
            for (int j = 0; j < 4; j++)
                bp[j] = *(const unsigned long long*)&Bs[cur][kk][tx2 + 32 * j];
#pragma unroll
            for (int i = 0; i < 8; i++) {
                unsigned long long aa;
                dup2(aa, af[i]);
                fma2(accp[i][0], aa, bp[0], accp[i][0]);
                fma2(accp[i][1], aa, bp[1], accp[i][1]);
                fma2(accp[i][2], aa, bp[2], accp[i][2]);
                fma2(accp[i][3], aa, bp[3], accp[i][3]);
            }
        }
        if (k0 < 15) {
            const int nxt = cur ^ 1;
            As[nxt][akc+0][arow] = a0.x; As[nxt][akc+1][arow] = a0.y;
            As[nxt][akc+2][arow] = a0.z; As[nxt][akc+3][arow] = a0.w;
            As[nxt][akc+4][arow] = a1.x; As[nxt][akc+5][arow] = a1.y;
            As[nxt][akc+6][arow] = a1.z; As[nxt][akc+7][arow] = a1.w;
            *(float4*)&Bs[nxt][bkr][bcol]     = b0;
            *(float4*)&Bs[nxt][bkr][bcol + 4] = b1;
        }
        __syncthreads();
    }

    float2 bj[4];
#pragma unroll
    for (int j = 0; j < 4; j++) {
        bj[j].x = bias[nb * DIN + n0 + tx2 + 32 * j];
        bj[j].y = bias[nb * DIN + n0 + tx2 + 32 * j + 1];
    }

#pragma unroll
    for (int i = 0; i < 8; i++) {
        const long row = m0 + ty * 8 + i;
        float* yp = Y + row * E_ + nb * DIN + n0;
#pragma unroll
        for (int j = 0; j < 4; j++) {
            float lo, hi;
            unpack2(lo, hi, accp[i][j]);
            *(float2*)(yp + tx2 + 32 * j) =
                make_float2((lo + bj[j].x) * scale, (hi + bj[j].y) * scale);
        }
    }
}

__global__ void __launch_bounds__(256) qkv_gemm(
    const float* __restrict__ Q, const float* __restrict__ Kin,
    const float* __restrict__ V,
    const float* __restrict__ Wq, const float* __restrict__ bq,
    const float* __restrict__ Wk, const float* __restrict__ bk,
    const float* __restrict__ Wv, const float* __restrict__ bv,
    float* __restrict__ Yq, float* __restrict__ Yk, float* __restrict__ Yv)
{
    const int op = blockIdx.z >> 2;
    const int nb = blockIdx.z & 3;
    if (op == 0)      gemm_core(Q,   Wq, bq, Yq, SCALING, nb);
    else if (op == 1) gemm_core(Kin, Wk, bk, Yk, 1.0f,    nb);
    else              gemm_core(V,   Wv, bv, Yv, 1.0f,    nb);
}

__global__ void __launch_bounds__(256) o_gemm(
    const float* __restrict__ X, const float* __restrict__ W,
    const float* __restrict__ bias, float* __restrict__ Y)
{
    gemm_core(X, W, bias, Y, 1.0f, blockIdx.z);
}

// =====================================================================
// Fused attention — R12 EXACT structure (proven best), with the loader
// issuing all 8 LDG.128 before the 8 STS (MLP=8; no other change).
// =====================================================================
#define QT  16
#define KT  128
#define SP  1032
#define NTH 256

__device__ __forceinline__ unsigned fmono(float f) {
    unsigned b = __float_as_uint(f);
    return (b & 0x80000000u) ? ~b : (b | 0x80000000u);
}
__device__ __forceinline__ float fdemono(unsigned m) {
    unsigned b = (m & 0x80000000u) ? (m & 0x7fffffffu) : ~m;
    return __uint_as_float(b);
}

// branchless sorted-top4 insertion; strict > keeps earliest pos on ties
#define INS4(nv, np)                                                   \
    do {                                                               \
        bool c0 = (nv) > v0, c1 = (nv) > v1,                           \
             c2 = (nv) > v2, c3 = (nv) > v3;                           \
        v3 = c3 ? (c2 ? v2 : (nv)) : v3;                               \
        p3 = c3 ? (c2 ? p2 : (np)) : p3;                               \
        v2 = c2 ? (c1 ? v1 : (nv)) : v2;                               \
        p2 = c2 ? (c1 ? p1 : (np)) : p2;                               \
        v1 = c1 ? (c0 ? v0 : (nv)) : v1;                               \
        p1 = c1 ? (c0 ? p0 : (np)) : p1;                               \
        v0 = c0 ? (nv) : v0;                                           \
        p0 = c0 ? (np) : p0;                                           \
    } while (0)

// strided conflict-free scan (positions ascend per lane -> min-pos ties)
#define SCAN_TOP4(Sr)                                                  \
    do {                                                               \
        v0 = v1 = v2 = v3 = -INFINITY;                                 \
        p0 = p1 = p2 = p3 = 0;                                         \
        _Pragma("unroll")                                              \
        for (int t = 0; t < 32; t++) {                                 \
            float nv = (Sr)[lane + 32 * t];                            \
            int   np = lane + 32 * t;                                  \
            INS4(nv, np);                                              \
        }                                                              \
    } while (0)

__global__ void __launch_bounds__(NTH, 2) attn_kernel(
    const float* __restrict__ qg, const float* __restrict__ kg,
    const float* __restrict__ vg, float* __restrict__ ctxg)
{
    extern __shared__ float sm[];
    float* S    = sm;                      // QT*SP              (66048 B)
    float* ks   = S + QT * SP;             // 128 x 64 swizzled  (32768 B)
    float* qp   = ks + KT * 64;            // [d][pair] 64 x 8 x float2 (4096 B)
    float* tpp  = qp + 64 * 8 * 2;         // QT*16
    int*   tpi  = (int*)(tpp + QT * TOPK); // QT*16

    const int tid = threadIdx.x;
    const int qt  = blockIdx.x;            // 0..63
    const int bh  = blockIdx.y;            // 0..127
    const int bb  = bh >> 4;
    const int hh  = bh & 15;
    const long base = (long)bb * E_ + hh * HD;

    const int lane = tid & 31;
    const int w    = tid >> 5;             // warp 0..7

    // ---- build q pairs: qp[(d*8+p)*2] = {q[2p][d], q[2p+1][d]} ----
#pragma unroll
    for (int e = tid; e < 512; e += NTH) {
        const int p = e >> 6;              // 0..7
        const int d = e & 63;
        const float* q0 = qg + (long)(qt * QT + 2 * p) * BE + base + d;
        *(float2*)&qp[(d * 8 + p) * 2] = make_float2(q0[0], q0[BE]);
    }

    // score warp roles (w<4): g = pair group (pairs g*4..g*4+3), s = key half
    const int g = (w >> 1) & 1;
    const int s = w & 1;
    const int lane7 = lane & 7;
    const float* ka_ptr = ks + (s * 64 + lane) * 64;
    const float* kb_ptr = ka_ptr + 32 * 64;

    // loader ownership: thread covers f = tid + 256*u, u = 0..7
    for (int kt = 0; kt < T_ / KT; kt++) {
        __syncthreads();
        {
            const float* kgt = kg + (long)(kt * KT) * BE + base;
            float4 ld[8];
#pragma unroll
            for (int u = 0; u < 8; u++) {
                int f = tid + NTH * u;
                int key = f >> 4, d4x = f & 15;
                ld[u] = *(const float4*)(kgt + (long)key * BE + d4x * 4);
            }
#pragma unroll
            for (int u = 0; u < 8; u++) {
                int f = tid + NTH * u;
                int key = f >> 4, d4x = f & 15;
                *(float4*)&ks[key * 64 + ((d4x ^ (key & 7)) << 2)] = ld[u];
            }
        }
        __syncthreads();

        if (w < 4) {
            unsigned long long acc[4][2];
#pragma unroll
            for (int p = 0; p < 4; p++) { acc[p][0] = 0ull; acc[p][1] = 0ull; }

#pragma unroll
            for (int d4 = 0; d4 < 16; d4++) {
                const int c = (d4 ^ lane7) << 2;
                float4 Ka = *(const float4*)(ka_ptr + c);
                float4 Kb = *(const float4*)(kb_ptr + c);
#pragma unroll
                for (int dd = 0; dd < 4; dd++) {
                    unsigned long long kda, kdb;
                    dup2(kda, (&Ka.x)[dd]);
                    dup2(kdb, (&Kb.x)[dd]);
                    const float* qpd = qp + (((d4 * 4 + dd) * 8) + g * 4) * 2;
                    ulonglong2 q01 = *(const ulonglong2*)(qpd);
                    ulonglong2 q23 = *(const ulonglong2*)(qpd + 4);
                    fma2(acc[0][0], q01.x, kda, acc[0][0]);
                    fma2(acc[0][1], q01.x, kdb, acc[0][1]);
                    fma2(acc[1][0], q01.y, kda, acc[1][0]);
                    fma2(acc[1][1], q01.y, kdb, acc[1][1]);
                    fma2(acc[2][0], q23.x, kda, acc[2][0]);
                    fma2(acc[2][1], q23.x, kdb, acc[2][1]);
                    fma2(acc[3][0], q23.y, kda, acc[3][0]);
                    fma2(acc[3][1], q23.y, kdb, acc[3][1]);
                }
            }

            const int col = kt * KT + s * 64 + lane;
#pragma unroll
            for (int p = 0; p < 4; p++) {
                float lo, hi;
                unpack2(lo, hi, acc[p][0]);
                S[(g * 8 + 2 * p    ) * SP + col] = lo;
                S[(g * 8 + 2 * p + 1) * SP + col] = hi;
                unpack2(lo, hi, acc[p][1]);
                S[(g * 8 + 2 * p    ) * SP + col + 32] = lo;
                S[(g * 8 + 2 * p + 1) * SP + col + 32] = hi;
            }
        }
    }
    __syncthreads();

    // ---- per-row top-16 + softmax: warp w owns rows 2w, 2w+1 ----
    for (int r = w * 2; r < w * 2 + 2; r++) {
        float* Sr = S + r * SP;

        float v0, v1, v2, v3;
        int   p0, p1, p2, p3;
        SCAN_TOP4(Sr);
        int cnt = 4;

        unsigned kb = fmono(v0);
        unsigned mk = __reduce_max_sync(0xffffffffu, kb);
        unsigned cp = (kb == mk) ? (unsigned)p0 : 0xffffffffu;
        unsigned bp = __reduce_min_sync(0xffffffffu, cp);
        const float m = fdemono(mk);

        // softmax denominator — EXACT established pattern (bitwise identical)
        float s0 = 0.f, s1 = 0.f, s2 = 0.f, s3 = 0.f;
#pragma unroll
        for (int t = 0; t < 32; t += 4) {
            s0 += __expf(Sr[lane + 32 * (t + 0)] - m);
            s1 += __expf(Sr[lane + 32 * (t + 1)] - m);
            s2 += __expf(Sr[lane + 32 * (t + 2)] - m);
            s3 += __expf(Sr[lane + 32 * (t + 3)] - m);
        }
        float sum = (s0 + s1) + (s2 + s3);
#pragma unroll
        for (int o = 16; o; o >>= 1) sum += __shfl_xor_sync(~0u, sum, o);
        const float inv = 1.0f / sum;

        if (lane == 0) { tpi[r * TOPK] = (int)bp; tpp[r * TOPK] = inv; }
        if ((int)(bp & 31) == lane) {
            Sr[bp] = -INFINITY;
            v0=v1;p0=p1; v1=v2;p1=p2; v2=v3;p2=p3; v3=-INFINITY;
            if (--cnt == 0) { SCAN_TOP4(Sr); cnt = 4; }
        }

        for (int it = 1; it < TOPK; it++) {
            kb = fmono(v0);
            mk = __reduce_max_sync(0xffffffffu, kb);
            cp = (kb == mk) ? (unsigned)p0 : 0xffffffffu;
            bp = __reduce_min_sync(0xffffffffu, cp);
            if (lane == 0) {
                tpi[r * TOPK + it] = (int)bp;
                tpp[r * TOPK + it] = __expf(fdemono(mk) - m) * inv;
            }
            if ((int)(bp & 31) == lane) {
                Sr[bp] = -INFINITY;
                v0=v1;p0=p1; v1=v2;p1=p2; v2=v3;p2=p3; v3=-INFINITY;
                if (--cnt == 0) { SCAN_TOP4(Sr); cnt = 4; }
            }
        }
    }
    __syncthreads();

    // ---- sparse ctx: 16-key gather; 16 threads x float4 per row ----
    const int cr = tid >> 4;               // 0..15 query row
    const int d0 = (tid & 15) * 4;         // 0..60
    float c0 = 0.f, c1 = 0.f, c2 = 0.f, c3 = 0.f;
#pragma unroll
    for (int i = 0; i < TOPK; i++) {
        const int   idx = tpi[cr * TOPK + i];
        const float p   = tpp[cr * TOPK + i];
        float4 a = *(const float4*)(vg + (long)idx * BE + base + d0);
        c0 = fmaf(p, a.x, c0); c1 = fmaf(p, a.y, c1);
        c2 = fmaf(p, a.z, c2); c3 = fmaf(p, a.w, c3);
    }
    *(float4*)(ctxg + (long)(qt * QT + cr) * BE + base + d0) =
        make_float4(c0, c1, c2, c3);
}

// =====================================================================
// launch
// =====================================================================
static const size_t ATTN_SMEM =
    (size_t)(QT * SP + KT * 64 + 64 * 8 * 2 + QT * TOPK + QT * TOPK) * 4;

extern "C" void kernel_launch(void* const* d_in, const int* in_sizes, int n_in,
                              void* d_out, int out_size)
{
    const float* query  = (const float*)d_in[0];
    const float* key_in = (const float*)d_in[1];
    const float* value  = (const float*)d_in[2];
    const float* Wq = (const float*)d_in[3];
    const float* bq = (const float*)d_in[4];
    const float* Wk = (const float*)d_in[5];
    const float* bk = (const float*)d_in[6];
    const float* Wv = (const float*)d_in[7];
    const float* bv = (const float*)d_in[8];
    const float* Wo = (const float*)d_in[9];
    const float* bo = (const float*)d_in[10];
    float* out = (float*)d_out;

    float *pq, *pk, *pv, *pctx;
    cudaGetSymbolAddress((void**)&pq,   g_q);
    cudaGetSymbolAddress((void**)&pk,   g_k);
    cudaGetSymbolAddress((void**)&pv,   g_v);
    cudaGetSymbolAddress((void**)&pctx, g_ctx);

    cudaFuncSetAttribute(attn_kernel,
                         cudaFuncAttributeMaxDynamicSharedMemorySize,
                         (int)ATTN_SMEM);

    dim3 gq(ROWS / 128, DIN / 128, 12);
    qkv_gemm<<<gq, 256>>>(query, key_in, value,
                          Wq, bq, Wk, bk, Wv, bv, pq, pk, pv);

    dim3 ag(T_ / QT, B_ * H_);
    attn_kernel<<<ag, NTH, ATTN_SMEM>>>(pq, pk, pv, pctx);

    dim3 go(ROWS / 128, DIN / 128, NB);
    o_gemm<<<go, 256>>>(pctx, Wo, bo, out);
}